// round 3
// baseline (speedup 1.0000x reference)
#include <cuda_runtime.h>

typedef unsigned long long ull;

#define NTHREADS 256
#define ROWS_PER_CTA 4     // 8 warps = 4 warp-pairs, one row per pair
#define NROW 2304          // 36 * 64
#define HK 36
#define HALF 18            // blocks per warp
#define QP 9               // P/M pairs per warp

// ---------------------------------------------------------------------------
// H36 sign masks, bit j set <=> entry (k, j) == '-'. Transcribed verbatim
// from the reference _H36 (validated by rel_err 1e-7 in prior rounds).
// ---------------------------------------------------------------------------
__host__ __device__ constexpr ull rowmask(const char* s) {
    ull m = 0;
    for (int j = 0; j < 36; j++) if (s[j] == '-') m |= (1ull << j);
    return m;
}

constexpr ull RM[HK] = {
    rowmask("++++++++++++++++++-+++++++++++++++++"),
    rowmask("++++-+---++---+-+++-++-+---++---+-++"),
    rowmask("+++++-+---++---+-+++-++-+---++---+-+"),
    rowmask("++++++-+---++---+-+++-++-+---++---+-"),
    rowmask("+-+++++-+---++---++-++-++-+---++---+"),
    rowmask("++-+++++-+---++---++-++-++-+---++---"),
    rowmask("+-+-+++++-+---++--+-+-++-++-+---++--"),
    rowmask("+--+-+++++-+---++-+--+-++-++-+---++-"),
    rowmask("+---+-+++++-+---+++---+-++-++-+---++"),
    rowmask("++---+-+++++-+---+++---+-++-++-+---+"),
    rowmask("+++---+-+++++-+---+++---+-++-++-+---"),
    rowmask("+-++---+-+++++-+--+-++---+-++-++-+--"),
    rowmask("+--++---+-+++++-+-+--++---+-++-++-+-"),
    rowmask("+---++---+-+++++-++---++---+-++-++-+"),
    rowmask("++---++---+-+++++-++---++---+-++-++-"),
    rowmask("+-+---++---+-++++++-+---++---+-++-++"),
    rowmask("++-+---++---+-++++++-+---++---+-++-+"),
    rowmask("+++-+---++---+-++++++-+---++---+-++-"),
    rowmask("-+++++++++++++++++------------------"),
    rowmask("+-++-+---++---+-++----+-+++--+++-+--"),
    rowmask("++-++-+---++---+-+-----+-+++--+++-+-"),
    rowmask("+++-++-+---++---+-------+-+++--+++-+"),
    rowmask("+-++-++-+---++---+-+-----+-+++--+++-"),
    rowmask("++-++-++-+---++-----+-----+-+++--+++"),
    rowmask("+-+-++-++-+---++---+-+-----+-+++--++"),
    rowmask("+--+-++-++-+---++--++-+-----+-+++--+"),
    rowmask("+---+-++-++-+---++-+++-+-----+-+++--"),
    rowmask("++---+-++-++-+---+--+++-+-----+-+++-"),
    rowmask("+++---+-++-++-+------+++-+-----+-+++"),
    rowmask("+-++---+-++-++-+---+--+++-+-----+-++"),
    rowmask("+--++---+-++-++-+--++--+++-+-----+-+"),
    rowmask("+---++---+-++-++-+-+++--+++-+-----+-"),
    rowmask("++---++---+-++-++---+++--+++-+-----+"),
    rowmask("+-+---++---+-++-++-+-+++--+++-+-----"),
    rowmask("++-+---++---+-++-+--+-+++--+++-+----"),
    rowmask("+++-+---++---+-++----+-+++--+++-+---"),
};

// ---------------------------------------------------------------------------
// packed f32x2 helpers (sm_10x FFMA2 path, PTX-only)
// ---------------------------------------------------------------------------
__device__ __forceinline__ ull pk2(float x, float y) {
    ull r; asm("mov.b64 %0, {%1, %2};" : "=l"(r) : "f"(x), "f"(y)); return r;
}
__device__ __forceinline__ float2 upk2(ull v) {
    float2 f; asm("mov.b64 {%0, %1}, %2;" : "=f"(f.x), "=f"(f.y) : "l"(v)); return f;
}
__device__ __forceinline__ ull fma2(ull a, ull b, ull c) {
    ull d; asm("fma.rn.f32x2 %0, %1, %2, %3;" : "=l"(d) : "l"(a), "l"(b), "l"(c)); return d;
}
__device__ __forceinline__ ull add2(ull a, ull b) {
    ull d; asm("add.rn.f32x2 %0, %1, %2;" : "=l"(d) : "l"(a), "l"(b)); return d;
}
__device__ __forceinline__ ull mul2(ull a, ull b) {
    ull d; asm("mul.rn.f32x2 %0, %1, %2;" : "=l"(d) : "l"(a), "l"(b)); return d;
}

// ---------------------------------------------------------------------------
// Partial mix for output row K over this warp's 9 P/M pairs (pairs H*9..H*9+8).
// Signs use the globally-flipped mask (first '+' convention); the finalizing
// warp applies the matching +-1/48 scale.
// ---------------------------------------------------------------------------
template<int K, int H>
__device__ __forceinline__ ull partial_pm(const ull (&P)[QP], const ull (&M)[QP],
                                          ull MONE) {
    constexpr ull rm0 = RM[K];
    constexpr ull rm  = (rm0 & 1ull) ? ~rm0 : rm0;
    ull acc;
    {
        constexpr int p  = H * QP;
        constexpr int b0 = (int)((rm >> (2 * p)) & 1);
        constexpr int b1 = (int)((rm >> (2 * p + 1)) & 1);
        acc = (b0 ^ b1) ? M[0] : P[0];
        if constexpr (b0 != 0) acc = mul2(acc, MONE);
    }
    #pragma unroll
    for (int q = 1; q < QP; q++) {
        const int p  = H * QP + q;
        const int b0 = (int)((rm >> (2 * p)) & 1);
        const int b1 = (int)((rm >> (2 * p + 1)) & 1);
        const ull term = (b0 ^ b1) ? M[q] : P[q];
        if (b0) acc = fma2(term, MONE, acc);
        else    acc = add2(acc, term);
    }
    return acc;
}

// Compute partials for the 18 k's the PARTNER finalizes; store to smem.
template<int I, int H>
__device__ __forceinline__ void foreign_loop(const ull (&P)[QP], const ull (&M)[QP],
                                             ull* s_pair, int lane, ull MONE) {
    if constexpr (I < HALF) {
        constexpr int K = (H ^ 1) * HALF + I;
        s_pair[K * 32 + lane] = partial_pm<K, H>(P, M, MONE);
        foreign_loop<I + 1, H>(P, M, s_pair, lane, MONE);
    }
}

// Finalize the 18 k's this warp owns: own partial + partner partial, scale, store.
template<int I, int H>
__device__ __forceinline__ void own_loop(const ull (&P)[QP], const ull (&M)[QP],
                                         const ull* s_pair, float* __restrict__ orow,
                                         int lane, ull MONE, ull SC, ull NSC) {
    if constexpr (I < HALF) {
        constexpr int K = H * HALF + I;
        ull mine  = partial_pm<K, H>(P, M, MONE);
        ull other = s_pair[K * 32 + lane];
        ull tot   = add2(mine, other);
        constexpr bool flip = (RM[K] & 1ull) != 0;
        ull res = mul2(tot, flip ? NSC : SC);
        float2 r = upk2(res);
        ((float2*)(orow + K * 64))[lane] = r;
        own_loop<I + 1, H>(P, M, s_pair, orow, lane, MONE, SC, NSC);
    }
}

template<int H>
__device__ __forceinline__ void do_row(const float* __restrict__ xr,
                                       float* __restrict__ orow,
                                       ull* s_pair, int lane, bool active) {
    const ull ONE  = pk2(1.0f, 1.0f);
    const ull MONE = pk2(-1.0f, -1.0f);
    const ull SC   = pk2( 1.0f / 48.0f,  1.0f / 48.0f);
    const ull NSC  = pk2(-1.0f / 48.0f, -1.0f / 48.0f);
    ull sg0 = (lane & 1)  ? MONE : ONE;
    ull sg1 = (lane & 2)  ? MONE : ONE;
    ull sg2 = (lane & 4)  ? MONE : ONE;
    ull sg3 = (lane & 8)  ? MONE : ONE;
    ull sg4 = (lane & 16) ? MONE : ONE;

    ull P[QP], M[QP];
    if (active) {
        // ---- Phase 1: FWHT-64 on this warp's 18 blocks (j = H*18 .. H*18+17).
        // Lane l holds m = {2l, 2l+1}; Walsh natural order preserved.
        #pragma unroll
        for (int q = 0; q < QP; q++) {
            ull tpair[2];
            #pragma unroll
            for (int h2 = 0; h2 < 2; h2++) {
                const int j = H * HALF + 2 * q + h2;
                float2 v = __ldg((const float2*)(xr + j * 64) + lane);
                ull tv = pk2(v.x + v.y, v.x - v.y);   // bit 0 (local)
                {
                    float2 f = upk2(tv);
                    ull w = pk2(__shfl_xor_sync(0xffffffffu, f.x, 1),
                                __shfl_xor_sync(0xffffffffu, f.y, 1));
                    tv = fma2(tv, sg0, w);
                }
                {
                    float2 f = upk2(tv);
                    ull w = pk2(__shfl_xor_sync(0xffffffffu, f.x, 2),
                                __shfl_xor_sync(0xffffffffu, f.y, 2));
                    tv = fma2(tv, sg1, w);
                }
                {
                    float2 f = upk2(tv);
                    ull w = pk2(__shfl_xor_sync(0xffffffffu, f.x, 4),
                                __shfl_xor_sync(0xffffffffu, f.y, 4));
                    tv = fma2(tv, sg2, w);
                }
                {
                    float2 f = upk2(tv);
                    ull w = pk2(__shfl_xor_sync(0xffffffffu, f.x, 8),
                                __shfl_xor_sync(0xffffffffu, f.y, 8));
                    tv = fma2(tv, sg3, w);
                }
                {
                    float2 f = upk2(tv);
                    ull w = pk2(__shfl_xor_sync(0xffffffffu, f.x, 16),
                                __shfl_xor_sync(0xffffffffu, f.y, 16));
                    tv = fma2(tv, sg4, w);
                }
                tpair[h2] = tv;
            }
            P[q] = add2(tpair[0], tpair[1]);
            M[q] = fma2(tpair[1], MONE, tpair[0]);
        }

        // ---- Phase 2a: partials for the partner's 18 k's -> smem.
        foreign_loop<0, H>(P, M, s_pair, lane, MONE);
    }

    __syncthreads();   // publish partials (BAR drains STS); all CTA warps arrive

    if (active) {
        // ---- Phase 2b: finalize own 18 k's.
        own_loop<0, H>(P, M, s_pair, orow, lane, MONE, SC, NSC);
    }
}

__global__ void __launch_bounds__(NTHREADS, 3)
hadamard_kernel(const float* __restrict__ x, float* __restrict__ out, int nrows) {
    // per warp-pair: 36 k-rows x 32 lanes x 8B partials
    __shared__ __align__(16) ull s_part[ROWS_PER_CTA][HK * 32];

    const int tid  = threadIdx.x;
    const int lane = tid & 31;
    const int warp = tid >> 5;
    const int pr   = warp >> 1;        // pair id within CTA (0..3)
    const int h    = warp & 1;         // half id within pair
    const int row  = blockIdx.x * ROWS_PER_CTA + pr;
    const bool active = row < nrows;

    const float* __restrict__ xr = x + (size_t)(active ? row : 0) * NROW;
    float* __restrict__ orow = out + (size_t)(active ? row : 0) * NROW;

    if (h == 0) do_row<0>(xr, orow, s_part[pr], lane, active);
    else        do_row<1>(xr, orow, s_part[pr], lane, active);
}

extern "C" void kernel_launch(void* const* d_in, const int* in_sizes, int n_in,
                              void* d_out, int out_size) {
    const float* x = (const float*)d_in[0];
    float* out = (float*)d_out;
    int nrows = in_sizes[0] / NROW;   // 32768

    int grid = (nrows + ROWS_PER_CTA - 1) / ROWS_PER_CTA;
    hadamard_kernel<<<grid, NTHREADS>>>(x, out, nrows);
}

// round 4
// speedup vs baseline: 1.1604x; 1.1604x over previous
#include <cuda_runtime.h>

typedef unsigned long long ull;

#define NTHREADS 128
#define RPC 4              // rows per CTA (one row per warp)
#define NROW 2304          // 36 * 64
#define HK 36

// ---------------------------------------------------------------------------
// H36 sign masks, bit j set <=> entry (k, j) == '-'. Transcribed verbatim
// from the reference _H36 (validated at rel_err ~1e-7 in prior rounds).
// ---------------------------------------------------------------------------
__host__ __device__ constexpr ull rowmask(const char* s) {
    ull m = 0;
    for (int j = 0; j < 36; j++) if (s[j] == '-') m |= (1ull << j);
    return m;
}

constexpr ull RM[HK] = {
    rowmask("++++++++++++++++++-+++++++++++++++++"),
    rowmask("++++-+---++---+-+++-++-+---++---+-++"),
    rowmask("+++++-+---++---+-+++-++-+---++---+-+"),
    rowmask("++++++-+---++---+-+++-++-+---++---+-"),
    rowmask("+-+++++-+---++---++-++-++-+---++---+"),
    rowmask("++-+++++-+---++---++-++-++-+---++---"),
    rowmask("+-+-+++++-+---++--+-+-++-++-+---++--"),
    rowmask("+--+-+++++-+---++-+--+-++-++-+---++-"),
    rowmask("+---+-+++++-+---+++---+-++-++-+---++"),
    rowmask("++---+-+++++-+---+++---+-++-++-+---+"),
    rowmask("+++---+-+++++-+---+++---+-++-++-+---"),
    rowmask("+-++---+-+++++-+--+-++---+-++-++-+--"),
    rowmask("+--++---+-+++++-+-+--++---+-++-++-+-"),
    rowmask("+---++---+-+++++-++---++---+-++-++-+"),
    rowmask("++---++---+-+++++-++---++---+-++-++-"),
    rowmask("+-+---++---+-++++++-+---++---+-++-++"),
    rowmask("++-+---++---+-++++++-+---++---+-++-+"),
    rowmask("+++-+---++---+-++++++-+---++---+-++-"),
    rowmask("-+++++++++++++++++------------------"),
    rowmask("+-++-+---++---+-++----+-+++--+++-+--"),
    rowmask("++-++-+---++---+-+-----+-+++--+++-+-"),
    rowmask("+++-++-+---++---+-------+-+++--+++-+"),
    rowmask("+-++-++-+---++---+-+-----+-+++--+++-"),
    rowmask("++-++-++-+---++-----+-----+-+++--+++"),
    rowmask("+-+-++-++-+---++---+-+-----+-+++--++"),
    rowmask("+--+-++-++-+---++--++-+-----+-+++--+"),
    rowmask("+---+-++-++-+---++-+++-+-----+-+++--"),
    rowmask("++---+-++-++-+---+--+++-+-----+-+++-"),
    rowmask("+++---+-++-++-+------+++-+-----+-+++"),
    rowmask("+-++---+-++-++-+---+--+++-+-----+-++"),
    rowmask("+--++---+-++-++-+--++--+++-+-----+-+"),
    rowmask("+---++---+-++-++-+-+++--+++-+-----+-"),
    rowmask("++---++---+-++-++---+++--+++-+-----+"),
    rowmask("+-+---++---+-++-++-+-+++--+++-+-----"),
    rowmask("++-+---++---+-++-+--+-+++--+++-+----"),
    rowmask("+++-+---++---+-++----+-+++--+++-+---"),
};

// ---------------------------------------------------------------------------
// packed f32x2 helpers (sm_10x FFMA2 path, PTX-only)
// ---------------------------------------------------------------------------
__device__ __forceinline__ ull pk2(float x, float y) {
    ull r; asm("mov.b64 %0, {%1, %2};" : "=l"(r) : "f"(x), "f"(y)); return r;
}
__device__ __forceinline__ float2 upk2(ull v) {
    float2 f; asm("mov.b64 {%0, %1}, %2;" : "=f"(f.x), "=f"(f.y) : "l"(v)); return f;
}
__device__ __forceinline__ ull fma2(ull a, ull b, ull c) {
    ull d; asm("fma.rn.f32x2 %0, %1, %2, %3;" : "=l"(d) : "l"(a), "l"(b), "l"(c)); return d;
}
__device__ __forceinline__ ull add2(ull a, ull b) {
    ull d; asm("add.rn.f32x2 %0, %1, %2;" : "=l"(d) : "l"(a), "l"(b)); return d;
}
__device__ __forceinline__ ull mul2(ull a, ull b) {
    ull d; asm("mul.rn.f32x2 %0, %1, %2;" : "=l"(d) : "l"(a), "l"(b)); return d;
}

// FWHT-64 for the packed pair this lane owns (elements {2l, 2l+1} of a block).
// bit 0 is local (one FFMA2 against a half-swap), bits 1..5 via shfl.bfly.
__device__ __forceinline__ ull fwht64(ull v, ull PM1, const ull (&sg)[5]) {
    float2 f0 = upk2(v);
    ull tv = fma2(v, PM1, pk2(f0.y, f0.x));   // {e+o, e-o}
    #pragma unroll
    for (int s = 0; s < 5; s++) {
        float2 f = upk2(tv);
        ull w = pk2(__shfl_xor_sync(0xffffffffu, f.x, 1 << s),
                    __shfl_xor_sync(0xffffffffu, f.y, 1 << s));
        tv = fma2(tv, sg[s], w);
    }
    return tv;
}

// ---------------------------------------------------------------------------
// Phase 2: out[k*64+m] = (+-1/48) * sum over pairs of {+-P, +-M}.
// After the in-place transform, t[2p] = P_p, t[2p+1] = M_p.
// ---------------------------------------------------------------------------
template<int K>
__device__ __forceinline__ void mix_all(const ull (&t)[HK], float* __restrict__ orow,
                                        int lane, ull SC, ull NSC, ull MONE) {
    if constexpr (K < HK) {
        constexpr ull rm0  = RM[K];
        constexpr bool flip = (rm0 & 1ull) != 0;
        constexpr ull rm   = flip ? ~rm0 : rm0;   // first sign now '+'

        // pair 0: b0 == 0 by construction
        ull acc = t[((rm >> 1) & 1)];
        #pragma unroll
        for (int p = 1; p < HK / 2; p++) {
            const int b0 = (int)((rm >> (2 * p)) & 1);
            const int b1 = (int)((rm >> (2 * p + 1)) & 1);
            const ull term = t[2 * p + (b0 ^ b1)];
            if (b0) acc = fma2(term, MONE, acc);
            else    acc = add2(acc, term);
        }
        ull res = mul2(acc, flip ? NSC : SC);
        float2 r = upk2(res);
        __stcs(((float2*)(orow + K * 64)) + lane, r);
        mix_all<K + 1>(t, orow, lane, SC, NSC, MONE);
    }
}

__global__ void __launch_bounds__(NTHREADS)
hadamard_kernel(const float* __restrict__ x, float* __restrict__ out, int nrows) {
    const int tid  = threadIdx.x;
    const int lane = tid & 31;
    const int warp = tid >> 5;
    const int row  = blockIdx.x * RPC + warp;
    if (row >= nrows) return;

    const float* __restrict__ xr = x + (size_t)row * NROW;
    float* __restrict__ orow = out + (size_t)row * NROW;

    const ull ONE  = pk2(1.0f, 1.0f);
    const ull MONE = pk2(-1.0f, -1.0f);
    const ull PM1  = pk2(1.0f, -1.0f);
    const ull SC   = pk2( 1.0f / 48.0f,  1.0f / 48.0f);
    const ull NSC  = pk2(-1.0f / 48.0f, -1.0f / 48.0f);
    ull sg[5];
    sg[0] = (lane & 1)  ? MONE : ONE;
    sg[1] = (lane & 2)  ? MONE : ONE;
    sg[2] = (lane & 4)  ? MONE : ONE;
    sg[3] = (lane & 8)  ? MONE : ONE;
    sg[4] = (lane & 16) ? MONE : ONE;

    // ---- Phase 0: front-batch ALL 36 loads (raw bits, no math in between)
    // -> 36 consecutive LDG.E.64 in SASS, maximal per-warp MLP.
    ull t[HK];
    const ull* __restrict__ xp = (const ull*)xr + lane;   // {2l, 2l+1} of block 0
    #pragma unroll
    for (int j = 0; j < HK; j++)
        t[j] = __ldcs(xp + j * 32);

    // ---- Phase 1: FWHT-64 per block, in place; fold pairs into P/M.
    // Lane l keeps m = {2l, 2l+1} (Walsh natural order preserved).
    #pragma unroll
    for (int p = 0; p < HK / 2; p++) {
        ull a = fwht64(t[2 * p],     PM1, sg);
        ull b = fwht64(t[2 * p + 1], PM1, sg);
        t[2 * p]     = add2(a, b);           // P_p
        t[2 * p + 1] = fma2(b, MONE, a);     // M_p
    }

    // ---- Phase 2: compile-time-signed H36 mix, scaled by +-1/48.
    mix_all<0>(t, orow, lane, SC, NSC, MONE);
}

extern "C" void kernel_launch(void* const* d_in, const int* in_sizes, int n_in,
                              void* d_out, int out_size) {
    const float* x = (const float*)d_in[0];
    float* out = (float*)d_out;
    int nrows = in_sizes[0] / NROW;   // 32768

    int grid = (nrows + RPC - 1) / RPC;
    hadamard_kernel<<<grid, NTHREADS>>>(x, out, nrows);
}

// round 5
// speedup vs baseline: 1.1862x; 1.0222x over previous
#include <cuda_runtime.h>

typedef unsigned long long ull;

#define NTHREADS 128
#define RPC 4              // rows per CTA (one row per warp)
#define NROW 2304          // 36 * 64
#define HK 36

// ---------------------------------------------------------------------------
// H36 sign masks, bit j set <=> entry (k, j) == '-'. Transcribed verbatim
// from the reference _H36 (validated at rel_err ~1e-7 in prior rounds).
// ---------------------------------------------------------------------------
__host__ __device__ constexpr ull rowmask(const char* s) {
    ull m = 0;
    for (int j = 0; j < 36; j++) if (s[j] == '-') m |= (1ull << j);
    return m;
}

constexpr ull RM[HK] = {
    rowmask("++++++++++++++++++-+++++++++++++++++"),
    rowmask("++++-+---++---+-+++-++-+---++---+-++"),
    rowmask("+++++-+---++---+-+++-++-+---++---+-+"),
    rowmask("++++++-+---++---+-+++-++-+---++---+-"),
    rowmask("+-+++++-+---++---++-++-++-+---++---+"),
    rowmask("++-+++++-+---++---++-++-++-+---++---"),
    rowmask("+-+-+++++-+---++--+-+-++-++-+---++--"),
    rowmask("+--+-+++++-+---++-+--+-++-++-+---++-"),
    rowmask("+---+-+++++-+---+++---+-++-++-+---++"),
    rowmask("++---+-+++++-+---+++---+-++-++-+---+"),
    rowmask("+++---+-+++++-+---+++---+-++-++-+---"),
    rowmask("+-++---+-+++++-+--+-++---+-++-++-+--"),
    rowmask("+--++---+-+++++-+-+--++---+-++-++-+-"),
    rowmask("+---++---+-+++++-++---++---+-++-++-+"),
    rowmask("++---++---+-+++++-++---++---+-++-++-"),
    rowmask("+-+---++---+-++++++-+---++---+-++-++"),
    rowmask("++-+---++---+-++++++-+---++---+-++-+"),
    rowmask("+++-+---++---+-++++++-+---++---+-++-"),
    rowmask("-+++++++++++++++++------------------"),
    rowmask("+-++-+---++---+-++----+-+++--+++-+--"),
    rowmask("++-++-+---++---+-+-----+-+++--+++-+-"),
    rowmask("+++-++-+---++---+-------+-+++--+++-+"),
    rowmask("+-++-++-+---++---+-+-----+-+++--+++-"),
    rowmask("++-++-++-+---++-----+-----+-+++--+++"),
    rowmask("+-+-++-++-+---++---+-+-----+-+++--++"),
    rowmask("+--+-++-++-+---++--++-+-----+-+++--+"),
    rowmask("+---+-++-++-+---++-+++-+-----+-+++--"),
    rowmask("++---+-++-++-+---+--+++-+-----+-+++-"),
    rowmask("+++---+-++-++-+------+++-+-----+-+++"),
    rowmask("+-++---+-++-++-+---+--+++-+-----+-++"),
    rowmask("+--++---+-++-++-+--++--+++-+-----+-+"),
    rowmask("+---++---+-++-++-+-+++--+++-+-----+-"),
    rowmask("++---++---+-++-++---+++--+++-+-----+"),
    rowmask("+-+---++---+-++-++-+-+++--+++-+-----"),
    rowmask("++-+---++---+-++-+--+-+++--+++-+----"),
    rowmask("+++-+---++---+-++----+-+++--+++-+---"),
};

// ---------------------------------------------------------------------------
// Compile-time verification of the Paley-type structure used in phase 2:
//   for k = 1..17, with L = low-18, R = high-18 of row k:
//     R == L with bit k flipped
//     row (k+18) == [ R, ~L ]
//   and first-column signs: rows 0..17, 19..35 start '+', row 18 starts '-'.
// If any of this fails the kernel does not compile.
// ---------------------------------------------------------------------------
constexpr unsigned MASK18 = 0x3FFFFu;
constexpr bool check_structure() {
    if ((RM[0] & 1ull) != 0) return false;
    if ((RM[18] & 1ull) != 1) return false;
    for (int k = 1; k <= 17; k++) {
        unsigned lo1 = (unsigned)(RM[k] & MASK18);
        unsigned hi1 = (unsigned)((RM[k] >> 18) & MASK18);
        unsigned lo2 = (unsigned)(RM[k + 18] & MASK18);
        unsigned hi2 = (unsigned)((RM[k + 18] >> 18) & MASK18);
        if (lo1 & 1u) return false;                     // '+' lead
        if (hi1 != (lo1 ^ (1u << k))) return false;     // R_k = L_k flip@k
        if (lo2 != hi1) return false;                   // L_{k+18} = R_k
        if (hi2 != ((~lo1) & MASK18)) return false;     // R_{k+18} = -L_k
    }
    return true;
}
static_assert(check_structure(), "H36 structure assumption violated");

// ---------------------------------------------------------------------------
// packed f32x2 helpers (sm_10x FFMA2 path, PTX-only)
// ---------------------------------------------------------------------------
__device__ __forceinline__ ull pk2(float x, float y) {
    ull r; asm("mov.b64 %0, {%1, %2};" : "=l"(r) : "f"(x), "f"(y)); return r;
}
__device__ __forceinline__ float2 upk2(ull v) {
    float2 f; asm("mov.b64 {%0, %1}, %2;" : "=f"(f.x), "=f"(f.y) : "l"(v)); return f;
}
__device__ __forceinline__ ull fma2(ull a, ull b, ull c) {
    ull d; asm("fma.rn.f32x2 %0, %1, %2, %3;" : "=l"(d) : "l"(a), "l"(b), "l"(c)); return d;
}
__device__ __forceinline__ ull add2(ull a, ull b) {
    ull d; asm("add.rn.f32x2 %0, %1, %2;" : "=l"(d) : "l"(a), "l"(b)); return d;
}
__device__ __forceinline__ ull mul2(ull a, ull b) {
    ull d; asm("mul.rn.f32x2 %0, %1, %2;" : "=l"(d) : "l"(a), "l"(b)); return d;
}

// FWHT-64 for the packed pair this lane owns (elements {2l, 2l+1} of a block).
// bit 0 is local (one FFMA2 against a half-swap), bits 1..5 via shfl.bfly.
__device__ __forceinline__ ull fwht64(ull v, ull PM1, const ull (&sg)[5]) {
    float2 f0 = upk2(v);
    ull tv = fma2(v, PM1, pk2(f0.y, f0.x));   // {e+o, e-o}
    #pragma unroll
    for (int s = 0; s < 5; s++) {
        float2 f = upk2(tv);
        ull w = pk2(__shfl_xor_sync(0xffffffffu, f.x, 1 << s),
                    __shfl_xor_sync(0xffffffffu, f.y, 1 << s));
        tv = fma2(tv, sg[s], w);
    }
    return tv;
}

// ---------------------------------------------------------------------------
// Masked sum of 9 P/M pairs starting at t[BASE]: sum_j sign(MK,j) * t_block_j
// where t[BASE+2p] = P_p, t[BASE+2p+1] = M_p. Requires bit0 of MK clear.
// ---------------------------------------------------------------------------
template<unsigned MK, int BASE>
__device__ __forceinline__ ull masked9(const ull (&t)[HK], ull MONE) {
    static_assert((MK & 1u) == 0, "lead sign must be +");
    ull acc = t[BASE + ((MK >> 1) & 1)];
    #pragma unroll
    for (int p = 1; p < 9; p++) {
        const int b0 = (int)((MK >> (2 * p)) & 1);
        const int b1 = (int)((MK >> (2 * p + 1)) & 1);
        const ull term = t[BASE + 2 * p + (b0 ^ b1)];
        if (b0) acc = fma2(term, MONE, acc);
        else    acc = add2(acc, term);
    }
    return acc;
}

// Generic single-row mix over all 18 pairs (used for k = 0 and k = 18).
template<int K>
__device__ __forceinline__ void mix_one(const ull (&t)[HK], float* __restrict__ orow,
                                        int lane, ull SC, ull NSC, ull MONE) {
    constexpr ull rm0  = RM[K];
    constexpr bool flip = (rm0 & 1ull) != 0;
    constexpr ull rm   = flip ? ~rm0 : rm0;
    ull acc = t[((rm >> 1) & 1)];
    #pragma unroll
    for (int p = 1; p < HK / 2; p++) {
        const int b0 = (int)((rm >> (2 * p)) & 1);
        const int b1 = (int)((rm >> (2 * p + 1)) & 1);
        const ull term = t[2 * p + (b0 ^ b1)];
        if (b0) acc = fma2(term, MONE, acc);
        else    acc = add2(acc, term);
    }
    float2 r = upk2(mul2(acc, flip ? NSC : SC));
    __stcs(((float2*)(orow + K * 64)) + lane, r);
}

// Output pair (k, k+18) for k = 1..17 via the shared (A, D) sums:
//   y_k     = A + D - 2*L[k]*v_k
//   y_{k+18}= A - D - 2*L[k]*u_k
// with 2*u_k = Pu_q +- Mu_q and 2*v_k = Pv_q +- Mv_q (q = k/2, '-' iff k odd).
template<int K>
__device__ __forceinline__ void mix_pair(const ull (&t)[HK], float* __restrict__ orow,
                                         int lane, ull SC, ull MONE) {
    constexpr unsigned mkL = (unsigned)(RM[K] & MASK18);
    constexpr bool neg  = ((mkL >> K) & 1u) != 0;  // L_k[k] == '-'
    constexpr bool odd  = (K & 1) != 0;
    constexpr int  q    = K >> 1;

    ull A = masked9<mkL, 0>(t, MONE);    // over u = blocks 0..17
    ull D = masked9<mkL, 18>(t, MONE);   // over v = blocks 18..35

    // 2*v_k and 2*u_k from P/M
    ull cv = odd ? fma2(t[18 + 2 * q + 1], MONE, t[18 + 2 * q])
                 : add2(t[18 + 2 * q], t[18 + 2 * q + 1]);
    ull cu = odd ? fma2(t[2 * q + 1], MONE, t[2 * q])
                 : add2(t[2 * q], t[2 * q + 1]);

    ull yk = add2(A, D);
    yk = neg ? add2(yk, cv) : fma2(cv, MONE, yk);
    float2 r0 = upk2(mul2(yk, SC));
    __stcs(((float2*)(orow + K * 64)) + lane, r0);

    ull ym = fma2(D, MONE, A);
    ym = neg ? add2(ym, cu) : fma2(cu, MONE, ym);
    float2 r1 = upk2(mul2(ym, SC));
    __stcs(((float2*)(orow + (K + 18) * 64)) + lane, r1);
}

template<int K>
__device__ __forceinline__ void mix_pairs(const ull (&t)[HK], float* __restrict__ orow,
                                          int lane, ull SC, ull MONE) {
    if constexpr (K <= 17) {
        mix_pair<K>(t, orow, lane, SC, MONE);
        mix_pairs<K + 1>(t, orow, lane, SC, MONE);
    }
}

__global__ void __launch_bounds__(NTHREADS)
hadamard_kernel(const float* __restrict__ x, float* __restrict__ out, int nrows) {
    const int tid  = threadIdx.x;
    const int lane = tid & 31;
    const int warp = tid >> 5;
    const int row  = blockIdx.x * RPC + warp;
    if (row >= nrows) return;

    const float* __restrict__ xr = x + (size_t)row * NROW;
    float* __restrict__ orow = out + (size_t)row * NROW;

    const ull ONE  = pk2(1.0f, 1.0f);
    const ull MONE = pk2(-1.0f, -1.0f);
    const ull PM1  = pk2(1.0f, -1.0f);
    const ull SC   = pk2( 1.0f / 48.0f,  1.0f / 48.0f);
    const ull NSC  = pk2(-1.0f / 48.0f, -1.0f / 48.0f);
    ull sg[5];
    sg[0] = (lane & 1)  ? MONE : ONE;
    sg[1] = (lane & 2)  ? MONE : ONE;
    sg[2] = (lane & 4)  ? MONE : ONE;
    sg[3] = (lane & 8)  ? MONE : ONE;
    sg[4] = (lane & 16) ? MONE : ONE;

    // ---- Phase 0: front-batch ALL 36 loads -> 36 consecutive LDG.E.64.
    ull t[HK];
    const ull* __restrict__ xp = (const ull*)xr + lane;   // {2l, 2l+1} of block 0
    #pragma unroll
    for (int j = 0; j < HK; j++)
        t[j] = __ldcs(xp + j * 32);

    // ---- Phase 1: FWHT-64 per block, in place; fold pairs into P/M.
    #pragma unroll
    for (int p = 0; p < HK / 2; p++) {
        ull a = fwht64(t[2 * p],     PM1, sg);
        ull b = fwht64(t[2 * p + 1], PM1, sg);
        t[2 * p]     = add2(a, b);           // P_p
        t[2 * p + 1] = fma2(b, MONE, a);     // M_p
    }

    // ---- Phase 2: structured H36 mix (rows 0/18 generic, pairs share A/D).
    mix_one<0>(t, orow, lane, SC, NSC, MONE);
    mix_one<18>(t, orow, lane, SC, NSC, MONE);
    mix_pairs<1>(t, orow, lane, SC, MONE);
}

extern "C" void kernel_launch(void* const* d_in, const int* in_sizes, int n_in,
                              void* d_out, int out_size) {
    const float* x = (const float*)d_in[0];
    float* out = (float*)d_out;
    int nrows = in_sizes[0] / NROW;   // 32768

    int grid = (nrows + RPC - 1) / RPC;
    hadamard_kernel<<<grid, NTHREADS>>>(x, out, nrows);
}